// round 11
// baseline (speedup 1.0000x reference)
#include <cuda_runtime.h>
#include <cuda_fp16.h>
#include <cstdint>

// ---------------- problem constants ----------------
#define B_     4
#define S_     16
#define NF     64            // frames = B*S
#define H_     32
#define W_     32
#define HW_    1024
#define CL_    64            // LSTM channels per layer; gate channels = 256
#define GST    1152          // gates scratch stride (18 N-tiles of 64)
#define NT     18            // N tiles per frame
#define PLST   1160          // halves per shifted plane (16B-aligned stride)
#define BST    72            // B smem row stride in halves

// ---------------- device scratch (static; no allocations) ----------------
__device__ float g_gates[(size_t)NF * 256 * GST];                 // conv outputs
// 7 shifted fp16 padded-plane copies of x and of h0 (+ front/tail guards)
__device__ __align__(16) __half g_x7[(size_t)NF * 32 * 7 * PLST + 64 + 2048];
__device__ __align__(16) __half g_h7[(size_t)NF * 64 * 7 * PLST + 64 + 2048];
// fragment-ordered fp16 exact-split weights:
// [chunk][mtile(2)][warp(4)][mt(2)][ks(4)][lane(32)][4 u32]  (k = [ah|al])
__device__ __align__(16) uint32_t g_wf0[9  * 8192];
__device__ __align__(16) uint32_t g_wf1[18 * 8192];

// taps in order {-35,-34,-33,-1,0,1,33,34,35}: shifted-copy index + extra offset
__constant__ int c_q[9]   = { 0, 1, 2, 2, 3, 4, 4, 5, 6 };
__constant__ int c_off[9] = { 0, 0, -32, 0, 0, 0, 32, 0, 0 };
__constant__ int c_tq[7]  = { -35, -34, -1, 0, 1, 34, 35 };   // shift of copy q

// ---------------- helpers ----------------
__device__ __forceinline__ float sigm(float x) { return 1.0f / (1.0f + __expf(-x)); }

__device__ __forceinline__ uint32_t smem_u32(const void* p) {
    uint32_t a;
    asm("{ .reg .u64 t; cvta.to.shared.u64 t, %1; cvt.u32.u64 %0, t; }" : "=r"(a) : "l"(p));
    return a;
}

__device__ __forceinline__ void ldsm4t(uint32_t r[4], uint32_t addr) {
    asm volatile("ldmatrix.sync.aligned.m8n8.x4.trans.shared.b16 {%0,%1,%2,%3}, [%4];"
        : "=r"(r[0]), "=r"(r[1]), "=r"(r[2]), "=r"(r[3]) : "r"(addr));
}

__device__ __forceinline__ void mma16816(float d[4], uint32_t a0, uint32_t a1,
                                         uint32_t a2, uint32_t a3,
                                         uint32_t b0, uint32_t b1) {
    asm volatile(
        "mma.sync.aligned.m16n8k16.row.col.f32.f16.f16.f32 "
        "{%0,%1,%2,%3}, {%4,%5,%6,%7}, {%8,%9}, {%0,%1,%2,%3};"
        : "+f"(d[0]), "+f"(d[1]), "+f"(d[2]), "+f"(d[3])
        : "r"(a0), "r"(a1), "r"(a2), "r"(a3), "r"(b0), "r"(b1));
}

// ---------------- prologue kernels ----------------
__global__ void k_zero() {
    const uint4 z = make_uint4(0, 0, 0, 0);
    uint4* a = (uint4*)g_x7;  const size_t n1 = sizeof(g_x7) / 16;
    uint4* b = (uint4*)g_h7;  const size_t n2 = sizeof(g_h7) / 16;
    for (size_t i = blockIdx.x * blockDim.x + threadIdx.x; i < n1 + n2;
         i += (size_t)gridDim.x * blockDim.x) {
        if (i < n1) a[i] = z; else b[i - n1] = z;
    }
}

// build 7 shifted fp16 copies of padded x planes
__global__ void k_fill_x7(const float* __restrict__ x) {
    __half* xb = g_x7 + 64;
    const int n = NF * 32 * HW_;
    for (int i = blockIdx.x * blockDim.x + threadIdx.x; i < n;
         i += gridDim.x * blockDim.x) {
        int plane = i >> 10, px = i & 1023;
        int r = px >> 5, c = px & 31;
        int p = (r + 1) * 34 + (c + 1);
        __half hv = __float2half_rn(x[i]);
        __half* base = xb + (size_t)plane * 7 * PLST;
#pragma unroll
        for (int q = 0; q < 7; ++q)
            base[q * PLST + p - c_tq[q]] = hv;
    }
}

// pack weights directly into mma A-fragment order.
// fragment layout (m16n8k16, row-major A): lane l, reg r:
//   row = (l>>2) + (r&1)*8 ; cols = (l&3)*2 + (r>>1)*8 + {0,1}
// k in [0,32) = ah(ci=k), k in [32,64) = al(ci=k-32); a = ah+al exactly.
__global__ void k_pack_wf(const float* __restrict__ w0, const float* __restrict__ w1) {
    const int n0 = 9 * 8192, n1 = 18 * 8192;
    for (int i = blockIdx.x * blockDim.x + threadIdx.x; i < n0 + n1;
         i += gridDim.x * blockDim.x) {
        bool l1sel = (i >= n0);
        int j = l1sel ? (i - n0) : i;
        int r     = j & 3;
        int lane  = (j >> 2) & 31;
        int ks    = (j >> 7) & 3;
        int mt    = (j >> 9) & 1;
        int w     = (j >> 10) & 3;
        int mtile = (j >> 12) & 1;
        int ch    = j >> 13;
        int row   = mtile * 128 + w * 32 + mt * 16 + (lane >> 2) + (r & 1) * 8;
        int kbase = ks * 16 + (lane & 3) * 2 + (r >> 1) * 8;
        uint32_t outv = 0;
#pragma unroll
        for (int h = 0; h < 2; ++h) {
            int k = kbase + h;
            int ci = k & 31;
            bool lo = (k >= 32);
            float v = l1sel
                ? w1[((size_t)row * 64 + (ch & 1) * 32 + ci) * 9 + (ch >> 1)]
                : w0[((size_t)row * 32 + ci) * 9 + ch];
            __half ah = __float2half_rn(v);
            __half val = lo ? __float2half_rn(v - __half2float(ah)) : ah;
            outv |= (uint32_t)__half_as_ushort(val) << (16 * h);
        }
        (l1sel ? g_wf1 : g_wf0)[j] = outv;
    }
}

// ---------------- GEMM kernel ----------------
// CTA = 128 threads (4 warps). Tile: M=128 gate channels x N=64 padded pixels,
// one frame. Chunks of 32 ci; K_eff=64 ([ah|al] x bh, bh fragments reused).
// A fragments straight from fragment-ordered gmem (L2-resident LDG.128);
// B software-pipelined (register prefetch distance 2, double-buffered smem),
// one __syncthreads per chunk.
template <int CPT>   // chunks per tap: 1 (CIN=32) or 2 (CIN=64)
__device__ __forceinline__ void gemm_body(const __half* __restrict__ bpl,
                                          const uint32_t* __restrict__ wf,
                                          float* __restrict__ gates)
{
    __shared__ __align__(16) __half sBt[2][32 * BST];   // 9.2 KB total

    const int tid  = threadIdx.x, w = tid >> 5, lane = tid & 31;
    const int frame = blockIdx.x / NT, ntile = blockIdx.x - frame * NT;
    const int mtile = blockIdx.y;
    const int p0 = ntile * 64;
    const int NCH = 9 * CPT;

    const size_t fbase = (size_t)frame * (CPT * 32) * 7;
    const int cis = tid >> 3, gs = tid & 7;      // staging coords: 16 ci x 8 chunks

    // B chunk load (global, coalesced 128-bit)
    auto loadB = [&](int ch, uint4& va, uint4& vb) {
        const int tap = (CPT == 1) ? ch : (ch >> 1);
        const int ci0 = (CPT == 1) ? 0 : ((ch & 1) * 32);
        const __half* bp = bpl + (fbase + (size_t)ci0 * 7 + c_q[tap]) * PLST
                         + p0 + c_off[tap];
        va = *(const uint4*)(bp + (size_t)cis * (7 * PLST) + gs * 8);
        vb = *(const uint4*)(bp + (size_t)(cis + 16) * (7 * PLST) + gs * 8);
    };

    float d[2][8][4];
#pragma unroll
    for (int mt = 0; mt < 2; ++mt)
#pragma unroll
        for (int nt = 0; nt < 8; ++nt)
#pragma unroll
            for (int q = 0; q < 4; ++q) d[mt][nt][q] = 0.0f;

    // ---- pipeline prologue: B(0) staged, B(1) in registers ----
    uint4 bva[2], bvb[2];
    loadB(0, bva[0], bvb[0]);
    loadB(1, bva[1], bvb[1]);
    *(uint4*)(sBt[0] + cis * BST + gs * 8) = bva[0];
    *(uint4*)(sBt[0] + (cis + 16) * BST + gs * 8) = bvb[0];
    __syncthreads();

#pragma unroll 1
    for (int ch = 0; ch < NCH; ++ch) {
        const int p = ch & 1;

        // ---- A fragments for this chunk: 8 independent LDG.128 (L2) ----
        const uint4* af = (const uint4*)wf
                        + ((size_t)(ch * 2 + mtile) * 4 + w) * 256 + lane;
        uint4 afr[2][4];
#pragma unroll
        for (int mt = 0; mt < 2; ++mt)
#pragma unroll
            for (int ks = 0; ks < 4; ++ks)
                afr[mt][ks] = af[(mt * 4 + ks) * 32];

        // ---- B fragments via ldmatrix.trans from this chunk's buffer ----
        const uint32_t sBu = smem_u32(sBt[p]);
        uint32_t bfr[2][4][4];
#pragma unroll
        for (int kk = 0; kk < 2; ++kk)
#pragma unroll
            for (int np = 0; np < 4; ++np) {
                int ci = kk * 16 + ((lane >> 3) & 1) * 8 + (lane & 7);
                int px = np * 16 + (lane >> 4) * 8;
                ldsm4t(bfr[kk][np], sBu + (uint32_t)(ci * BST + px) * 2);
            }

        // ---- stage B(ch+1) from registers; prefetch B(ch+2) ----
        if (ch + 1 < NCH) {
            __half* sb = sBt[p ^ 1];
            *(uint4*)(sb + cis * BST + gs * 8) = bva[p ^ 1];
            *(uint4*)(sb + (cis + 16) * BST + gs * 8) = bvb[p ^ 1];
        }
        if (ch + 2 < NCH) loadB(ch + 2, bva[p], bvb[p]);

        // ---- mma: 4 k-steps of 16 (ks 0,1 = ah*bh; ks 2,3 = al*bh) ----
#pragma unroll
        for (int ks = 0; ks < 4; ++ks) {
            const int kk = ks & 1;
#pragma unroll
            for (int mt = 0; mt < 2; ++mt) {
                const uint4 a = afr[mt][ks];
#pragma unroll
                for (int nt = 0; nt < 8; ++nt)
                    mma16816(d[mt][nt], a.x, a.y, a.z, a.w,
                             bfr[kk][nt >> 1][(nt & 1) * 2],
                             bfr[kk][nt >> 1][(nt & 1) * 2 + 1]);
            }
        }
        __syncthreads();
    }

    // ---- epilogue: D -> gates scratch ----
    const int g4 = lane >> 2, t4 = lane & 3;
#pragma unroll
    for (int mt = 0; mt < 2; ++mt) {
        size_t rowbase = (size_t)frame * 256 + mtile * 128 + w * 32 + mt * 16 + g4;
#pragma unroll
        for (int nt = 0; nt < 8; ++nt) {
            float* gp = gates + rowbase * GST + p0 + nt * 8 + t4 * 2;
            *(float2*)gp                     = make_float2(d[mt][nt][0], d[mt][nt][1]);
            *(float2*)(gp + 8 * (size_t)GST) = make_float2(d[mt][nt][2], d[mt][nt][3]);
        }
    }
}

__global__ void __launch_bounds__(128, 3)
k_gemm0() { gemm_body<1>(g_x7 + 64, g_wf0, g_gates); }

__global__ void __launch_bounds__(128, 3)
k_gemm1() { gemm_body<2>(g_h7 + 64, g_wf1, g_gates); }

// ---------------- scan kernels ----------------
// thread = (b, lstm-channel, interior pixel); loops s, cell state in register.
// PADOUT=true writes the 7 shifted fp16 plane copies for the next GEMM.
template <bool PADOUT>
__global__ void __launch_bounds__(256)
k_scan(const float* __restrict__ bias, float* __restrict__ out)
{
    int gtid = blockIdx.x * blockDim.x + threadIdx.x;  // 0 .. 262143
    int px = gtid & 1023;
    int ch = (gtid >> 10) & 63;
    int b  = gtid >> 16;
    int r = px >> 5, c = px & 31;
    int p = (r + 1) * 34 + (c + 1);

    float bi = __ldg(bias + ch);
    float bf = __ldg(bias + 64 + ch);
    float bo = __ldg(bias + 128 + ch);
    float bc = __ldg(bias + 192 + ch);

    float cst = 0.5f;
    __half* h7 = g_h7 + 64;

#pragma unroll 1
    for (int s = 0; s < S_; ++s) {
        int frame = b * S_ + s;
        const float* gg = g_gates + (size_t)frame * 256 * GST + p;
        float it = sigm(gg[(size_t)(ch)       * GST] + bi);
        float ft = sigm(gg[(size_t)(64 + ch)  * GST] + bf);
        float ot = sigm(gg[(size_t)(128 + ch) * GST] + bo);
        float cd =      gg[(size_t)(192 + ch) * GST] + bc;
        float gd = (cd >= 0.0f) ? (cd + 0.5f) : sigm(cd);
        float inv = 1.0f / (it + ft);
        cst = (ft * inv) * cst + (it * inv) * gd;
        float hv = ot * cst;
        if (PADOUT) {
            __half h16 = __float2half_rn(hv);
            __half* base = h7 + ((size_t)frame * CL_ + ch) * 7 * PLST;
#pragma unroll
            for (int q = 0; q < 7; ++q)
                base[q * PLST + p - c_tq[q]] = h16;
        } else {
            out[((size_t)frame * CL_ + ch) * HW_ + px] = hv;
        }
    }
}

// ---------------- launch ----------------
extern "C" void kernel_launch(void* const* d_in, const int* in_sizes, int n_in,
                              void* d_out, int out_size)
{
    const float* x  = (const float*)d_in[0];
    const float* w0 = (const float*)d_in[1];
    const float* b0 = (const float*)d_in[2];
    const float* w1 = (const float*)d_in[3];
    const float* b1 = (const float*)d_in[4];
    float* out = (float*)d_out;

    k_zero<<<4096, 256>>>();
    k_fill_x7<<<2048, 256>>>(x);
    k_pack_wf<<<512, 256>>>(w0, w1);

    dim3 gg(NF * NT, 2, 1);   // 1152 x 2 CTAs
    k_gemm0<<<gg, 128>>>();
    k_scan<true><<<1024, 256>>>(b0, nullptr);
    k_gemm1<<<gg, 128>>>();
    k_scan<false><<<1024, 256>>>(b1, out);
}

// round 12
// speedup vs baseline: 1.3605x; 1.3605x over previous
#include <cuda_runtime.h>
#include <cuda_fp16.h>
#include <cstdint>

// ---------------- problem constants ----------------
#define B_     4
#define S_     16
#define NF     64            // frames = B*S
#define H_     32
#define W_     32
#define HW_    1024
#define CL_    64            // LSTM channels per layer; gate channels = 256
#define GST    1152          // gates scratch stride (18 N-tiles of 64)
#define NT     18            // N tiles per frame
#define PLST   1160          // halves per shifted plane (16B-aligned stride)
#define BST    72            // B smem row stride in halves

// ---------------- device scratch (static; no allocations) ----------------
__device__ float g_gates[(size_t)NF * 256 * GST];                 // conv outputs
// 7 shifted fp16 padded-plane copies of x and of h0 (+ front/tail guards)
__device__ __align__(16) __half g_x7[(size_t)NF * 32 * 7 * PLST + 64 + 2048];
__device__ __align__(16) __half g_h7[(size_t)NF * 64 * 7 * PLST + 64 + 2048];
// fragment-ordered fp16 weights (single precision term):
// [chunk][mtile(2)][warp(4)][mt(2)][ks(2)][lane(32)][4 u32]
__device__ __align__(16) uint32_t g_wf0[9  * 4096];
__device__ __align__(16) uint32_t g_wf1[18 * 4096];

// taps in order {-35,-34,-33,-1,0,1,33,34,35}: shifted-copy index + extra offset
__constant__ int c_q[9]   = { 0, 1, 2, 2, 3, 4, 4, 5, 6 };
__constant__ int c_off[9] = { 0, 0, -32, 0, 0, 0, 32, 0, 0 };
__constant__ int c_tq[7]  = { -35, -34, -1, 0, 1, 34, 35 };   // shift of copy q

// ---------------- helpers ----------------
__device__ __forceinline__ float sigm(float x) { return 1.0f / (1.0f + __expf(-x)); }

__device__ __forceinline__ uint32_t smem_u32(const void* p) {
    uint32_t a;
    asm("{ .reg .u64 t; cvta.to.shared.u64 t, %1; cvt.u32.u64 %0, t; }" : "=r"(a) : "l"(p));
    return a;
}

__device__ __forceinline__ void ldsm4t(uint32_t r[4], uint32_t addr) {
    asm volatile("ldmatrix.sync.aligned.m8n8.x4.trans.shared.b16 {%0,%1,%2,%3}, [%4];"
        : "=r"(r[0]), "=r"(r[1]), "=r"(r[2]), "=r"(r[3]) : "r"(addr));
}

__device__ __forceinline__ void mma16816(float d[4], uint32_t a0, uint32_t a1,
                                         uint32_t a2, uint32_t a3,
                                         uint32_t b0, uint32_t b1) {
    asm volatile(
        "mma.sync.aligned.m16n8k16.row.col.f32.f16.f16.f32 "
        "{%0,%1,%2,%3}, {%4,%5,%6,%7}, {%8,%9}, {%0,%1,%2,%3};"
        : "+f"(d[0]), "+f"(d[1]), "+f"(d[2]), "+f"(d[3])
        : "r"(a0), "r"(a1), "r"(a2), "r"(a3), "r"(b0), "r"(b1));
}

// ---------------- prologue kernels ----------------
__global__ void k_zero() {
    const uint4 z = make_uint4(0, 0, 0, 0);
    uint4* a = (uint4*)g_x7;  const size_t n1 = sizeof(g_x7) / 16;
    uint4* b = (uint4*)g_h7;  const size_t n2 = sizeof(g_h7) / 16;
    for (size_t i = blockIdx.x * blockDim.x + threadIdx.x; i < n1 + n2;
         i += (size_t)gridDim.x * blockDim.x) {
        if (i < n1) a[i] = z; else b[i - n1] = z;
    }
}

// build 7 shifted fp16 copies of padded x planes
__global__ void k_fill_x7(const float* __restrict__ x) {
    __half* xb = g_x7 + 64;
    const int n = NF * 32 * HW_;
    for (int i = blockIdx.x * blockDim.x + threadIdx.x; i < n;
         i += gridDim.x * blockDim.x) {
        int plane = i >> 10, px = i & 1023;
        int r = px >> 5, c = px & 31;
        int p = (r + 1) * 34 + (c + 1);
        __half hv = __float2half_rn(x[i]);
        __half* base = xb + (size_t)plane * 7 * PLST;
#pragma unroll
        for (int q = 0; q < 7; ++q)
            base[q * PLST + p - c_tq[q]] = hv;
    }
}

// pack weights directly into mma A-fragment order (single fp16 term).
// fragment layout (m16n8k16, row-major A): lane l, reg r:
//   row = (l>>2) + (r&1)*8 ; cols = (l&3)*2 + (r>>1)*8 + {0,1}
__global__ void k_pack_wf(const float* __restrict__ w0, const float* __restrict__ w1) {
    const int n0 = 9 * 4096, n1 = 18 * 4096;
    for (int i = blockIdx.x * blockDim.x + threadIdx.x; i < n0 + n1;
         i += gridDim.x * blockDim.x) {
        bool l1sel = (i >= n0);
        int j = l1sel ? (i - n0) : i;
        int r     = j & 3;
        int lane  = (j >> 2) & 31;
        int ks    = (j >> 7) & 1;
        int mt    = (j >> 8) & 1;
        int w     = (j >> 9) & 3;
        int mtile = (j >> 11) & 1;
        int ch    = j >> 12;
        int row   = mtile * 128 + w * 32 + mt * 16 + (lane >> 2) + (r & 1) * 8;
        int kbase = ks * 16 + (lane & 3) * 2 + (r >> 1) * 8;
        uint32_t outv = 0;
#pragma unroll
        for (int h = 0; h < 2; ++h) {
            int ci = kbase + h;    // 0..31
            float v = l1sel
                ? w1[((size_t)row * 64 + (ch & 1) * 32 + ci) * 9 + (ch >> 1)]
                : w0[((size_t)row * 32 + ci) * 9 + ch];
            outv |= (uint32_t)__half_as_ushort(__float2half_rn(v)) << (16 * h);
        }
        (l1sel ? g_wf1 : g_wf0)[j] = outv;
    }
}

// ---------------- GEMM kernel ----------------
// CTA = 128 threads (4 warps). Tile: M=128 gate channels x N=64 padded pixels,
// one frame. Chunks of 32 ci (K=32, 2 k-steps). A fragments straight from
// fragment-ordered gmem (L2-resident LDG.128); B double-buffered in smem,
// one __syncthreads per chunk (implicit LDG/compute overlap).
template <int CPT>   // chunks per tap: 1 (CIN=32) or 2 (CIN=64)
__device__ __forceinline__ void gemm_body(const __half* __restrict__ bpl,
                                          const uint32_t* __restrict__ wf,
                                          float* __restrict__ gates)
{
    __shared__ __align__(16) __half sBt[2][32 * BST];   // 9.2 KB total

    const int tid  = threadIdx.x, w = tid >> 5, lane = tid & 31;
    const int frame = blockIdx.x / NT, ntile = blockIdx.x - frame * NT;
    const int mtile = blockIdx.y;
    const int p0 = ntile * 64;
    const int NCH = 9 * CPT;

    const size_t fbase = (size_t)frame * (CPT * 32) * 7;
    const int cis = tid >> 3, gs = tid & 7;      // staging coords: 16 ci x 8 chunks

    float d[2][8][4];
#pragma unroll
    for (int mt = 0; mt < 2; ++mt)
#pragma unroll
        for (int nt = 0; nt < 8; ++nt)
#pragma unroll
            for (int q = 0; q < 4; ++q) d[mt][nt][q] = 0.0f;

#pragma unroll 1
    for (int ch = 0; ch < NCH; ++ch) {
        const int p = ch & 1;
        const int tap = (CPT == 1) ? ch : (ch >> 1);
        const int ci0 = (CPT == 1) ? 0 : ((ch & 1) * 32);

        // ---- B loads (global, coalesced 128-bit) ----
        const __half* bp = bpl + (fbase + (size_t)ci0 * 7 + c_q[tap]) * PLST
                         + p0 + c_off[tap];
        uint4 v0 = *(const uint4*)(bp + (size_t)cis * (7 * PLST) + gs * 8);
        uint4 v1 = *(const uint4*)(bp + (size_t)(cis + 16) * (7 * PLST) + gs * 8);

        // ---- A fragments: 4 independent LDG.128 (L2-resident) ----
        const uint4* af = (const uint4*)wf
                        + ((size_t)(ch * 2 + mtile) * 4 + w) * 128 + lane;
        uint4 afr[2][2];
#pragma unroll
        for (int mt = 0; mt < 2; ++mt)
#pragma unroll
            for (int ks = 0; ks < 2; ++ks)
                afr[mt][ks] = af[(mt * 2 + ks) * 32];

        // ---- store B into this chunk's buffer ----
        __half* sb = sBt[p];
        *(uint4*)(sb + cis * BST + gs * 8) = v0;
        *(uint4*)(sb + (cis + 16) * BST + gs * 8) = v1;
        __syncthreads();

        // ---- B fragments via ldmatrix.trans ----
        const uint32_t sBu = smem_u32(sb);
        uint32_t bfr[2][4][4];
#pragma unroll
        for (int kk = 0; kk < 2; ++kk)
#pragma unroll
            for (int np = 0; np < 4; ++np) {
                int ci = kk * 16 + ((lane >> 3) & 1) * 8 + (lane & 7);
                int px = np * 16 + (lane >> 4) * 8;
                ldsm4t(bfr[kk][np], sBu + (uint32_t)(ci * BST + px) * 2);
            }

        // ---- mma: 2 k-steps of 16 ----
#pragma unroll
        for (int ks = 0; ks < 2; ++ks) {
#pragma unroll
            for (int mt = 0; mt < 2; ++mt) {
                const uint4 a = afr[mt][ks];
#pragma unroll
                for (int nt = 0; nt < 8; ++nt)
                    mma16816(d[mt][nt], a.x, a.y, a.z, a.w,
                             bfr[ks][nt >> 1][(nt & 1) * 2],
                             bfr[ks][nt >> 1][(nt & 1) * 2 + 1]);
            }
        }
    }

    // ---- epilogue: D -> gates scratch ----
    const int g4 = lane >> 2, t4 = lane & 3;
#pragma unroll
    for (int mt = 0; mt < 2; ++mt) {
        size_t rowbase = (size_t)frame * 256 + mtile * 128 + w * 32 + mt * 16 + g4;
#pragma unroll
        for (int nt = 0; nt < 8; ++nt) {
            float* gp = gates + rowbase * GST + p0 + nt * 8 + t4 * 2;
            *(float2*)gp                     = make_float2(d[mt][nt][0], d[mt][nt][1]);
            *(float2*)(gp + 8 * (size_t)GST) = make_float2(d[mt][nt][2], d[mt][nt][3]);
        }
    }
}

__global__ void __launch_bounds__(128, 4)
k_gemm0() { gemm_body<1>(g_x7 + 64, g_wf0, g_gates); }

__global__ void __launch_bounds__(128, 4)
k_gemm1() { gemm_body<2>(g_h7 + 64, g_wf1, g_gates); }

// ---------------- scan kernels ----------------
// thread = (b, lstm-channel, interior pixel); loops s, cell state in register.
// PADOUT=true writes the 7 shifted fp16 plane copies for the next GEMM.
template <bool PADOUT>
__global__ void __launch_bounds__(256)
k_scan(const float* __restrict__ bias, float* __restrict__ out)
{
    int gtid = blockIdx.x * blockDim.x + threadIdx.x;  // 0 .. 262143
    int px = gtid & 1023;
    int ch = (gtid >> 10) & 63;
    int b  = gtid >> 16;
    int r = px >> 5, c = px & 31;
    int p = (r + 1) * 34 + (c + 1);

    float bi = __ldg(bias + ch);
    float bf = __ldg(bias + 64 + ch);
    float bo = __ldg(bias + 128 + ch);
    float bc = __ldg(bias + 192 + ch);

    float cst = 0.5f;
    __half* h7 = g_h7 + 64;

#pragma unroll 1
    for (int s = 0; s < S_; ++s) {
        int frame = b * S_ + s;
        const float* gg = g_gates + (size_t)frame * 256 * GST + p;
        float it = sigm(gg[(size_t)(ch)       * GST] + bi);
        float ft = sigm(gg[(size_t)(64 + ch)  * GST] + bf);
        float ot = sigm(gg[(size_t)(128 + ch) * GST] + bo);
        float cd =      gg[(size_t)(192 + ch) * GST] + bc;
        float gd = (cd >= 0.0f) ? (cd + 0.5f) : sigm(cd);
        float inv = 1.0f / (it + ft);
        cst = (ft * inv) * cst + (it * inv) * gd;
        float hv = ot * cst;
        if (PADOUT) {
            __half h16 = __float2half_rn(hv);
            __half* base = h7 + ((size_t)frame * CL_ + ch) * 7 * PLST;
#pragma unroll
            for (int q = 0; q < 7; ++q)
                base[q * PLST + p - c_tq[q]] = h16;
        } else {
            out[((size_t)frame * CL_ + ch) * HW_ + px] = hv;
        }
    }
}

// ---------------- launch ----------------
extern "C" void kernel_launch(void* const* d_in, const int* in_sizes, int n_in,
                              void* d_out, int out_size)
{
    const float* x  = (const float*)d_in[0];
    const float* w0 = (const float*)d_in[1];
    const float* b0 = (const float*)d_in[2];
    const float* w1 = (const float*)d_in[3];
    const float* b1 = (const float*)d_in[4];
    float* out = (float*)d_out;

    k_zero<<<4096, 256>>>();
    k_fill_x7<<<2048, 256>>>(x);
    k_pack_wf<<<512, 256>>>(w0, w1);

    dim3 gg(NF * NT, 2, 1);   // 1152 x 2 CTAs
    k_gemm0<<<gg, 128>>>();
    k_scan<true><<<1024, 256>>>(b0, nullptr);
    k_gemm1<<<gg, 128>>>();
    k_scan<false><<<1024, 256>>>(b1, out);
}

// round 13
// speedup vs baseline: 1.5517x; 1.1405x over previous
#include <cuda_runtime.h>
#include <cuda_fp16.h>
#include <cstdint>

// ---------------- problem constants ----------------
#define B_     4
#define S_     16
#define NF     64            // frames = B*S
#define H_     32
#define W_     32
#define HW_    1024
#define CL_    64            // LSTM channels per layer; gate channels = 256
#define GST    1152          // gates scratch stride (18 N-tiles of 64)
#define NT     18            // N tiles per frame
#define PLST   1160          // halves per shifted plane (16B-aligned stride)
#define BST    72            // B smem row stride in halves

// ---------------- device scratch (static; no allocations) ----------------
// NOTE: __device__ globals are zero-initialized at module load. Interiors are
// rewritten every launch; halo/guard positions are NEVER written by any
// kernel, so they stay zero across all launches -> no zeroing pass needed.
__device__ float g_gates[(size_t)NF * 256 * GST];                 // conv outputs
// 7 shifted fp16 padded-plane copies of x and of h0 (+ front/tail guards)
__device__ __align__(16) __half g_x7[(size_t)NF * 32 * 7 * PLST + 64 + 2048];
__device__ __align__(16) __half g_h7[(size_t)NF * 64 * 7 * PLST + 64 + 2048];
// fragment-ordered fp16 weights (single precision term):
// [chunk][mtile(2)][warp(4)][mt(2)][ks(2)][lane(32)][4 u32]
__device__ __align__(16) uint32_t g_wf0[9  * 4096];
__device__ __align__(16) uint32_t g_wf1[18 * 4096];

// taps in order {-35,-34,-33,-1,0,1,33,34,35}: shifted-copy index + extra offset
__constant__ int c_q[9]   = { 0, 1, 2, 2, 3, 4, 4, 5, 6 };
__constant__ int c_off[9] = { 0, 0, -32, 0, 0, 0, 32, 0, 0 };
__constant__ int c_tq[7]  = { -35, -34, -1, 0, 1, 34, 35 };   // shift of copy q

// ---------------- helpers ----------------
__device__ __forceinline__ float sigm(float x) { return 1.0f / (1.0f + __expf(-x)); }

__device__ __forceinline__ uint32_t smem_u32(const void* p) {
    uint32_t a;
    asm("{ .reg .u64 t; cvta.to.shared.u64 t, %1; cvt.u32.u64 %0, t; }" : "=r"(a) : "l"(p));
    return a;
}

__device__ __forceinline__ void cp16(uint32_t saddr, const void* gptr) {
    asm volatile("cp.async.cg.shared.global [%0], [%1], 16;"
                 :: "r"(saddr), "l"(gptr) : "memory");
}
__device__ __forceinline__ void cp_commit() {
    asm volatile("cp.async.commit_group;" ::: "memory");
}
__device__ __forceinline__ void cp_wait2() {
    asm volatile("cp.async.wait_group 2;" ::: "memory");
}

__device__ __forceinline__ void ldsm4t(uint32_t r[4], uint32_t addr) {
    asm volatile("ldmatrix.sync.aligned.m8n8.x4.trans.shared.b16 {%0,%1,%2,%3}, [%4];"
        : "=r"(r[0]), "=r"(r[1]), "=r"(r[2]), "=r"(r[3]) : "r"(addr));
}

__device__ __forceinline__ void mma16816(float d[4], uint32_t a0, uint32_t a1,
                                         uint32_t a2, uint32_t a3,
                                         uint32_t b0, uint32_t b1) {
    asm volatile(
        "mma.sync.aligned.m16n8k16.row.col.f32.f16.f16.f32 "
        "{%0,%1,%2,%3}, {%4,%5,%6,%7}, {%8,%9}, {%0,%1,%2,%3};"
        : "+f"(d[0]), "+f"(d[1]), "+f"(d[2]), "+f"(d[3])
        : "r"(a0), "r"(a1), "r"(a2), "r"(a3), "r"(b0), "r"(b1));
}

// ---------------- prologue kernels ----------------
// build 7 shifted fp16 copies of padded x planes (interior positions only)
__global__ void k_fill_x7(const float* __restrict__ x) {
    __half* xb = g_x7 + 64;
    const int n = NF * 32 * HW_;
    for (int i = blockIdx.x * blockDim.x + threadIdx.x; i < n;
         i += gridDim.x * blockDim.x) {
        int plane = i >> 10, px = i & 1023;
        int r = px >> 5, c = px & 31;
        int p = (r + 1) * 34 + (c + 1);
        __half hv = __float2half_rn(x[i]);
        __half* base = xb + (size_t)plane * 7 * PLST;
#pragma unroll
        for (int q = 0; q < 7; ++q)
            base[q * PLST + p - c_tq[q]] = hv;
    }
}

// pack weights directly into mma A-fragment order (single fp16 term).
// fragment layout (m16n8k16, row-major A): lane l, reg r:
//   row = (l>>2) + (r&1)*8 ; cols = (l&3)*2 + (r>>1)*8 + {0,1}
__global__ void k_pack_wf(const float* __restrict__ w0, const float* __restrict__ w1) {
    const int n0 = 9 * 4096, n1 = 18 * 4096;
    for (int i = blockIdx.x * blockDim.x + threadIdx.x; i < n0 + n1;
         i += gridDim.x * blockDim.x) {
        bool l1sel = (i >= n0);
        int j = l1sel ? (i - n0) : i;
        int r     = j & 3;
        int lane  = (j >> 2) & 31;
        int ks    = (j >> 7) & 1;
        int mt    = (j >> 8) & 1;
        int w     = (j >> 9) & 3;
        int mtile = (j >> 11) & 1;
        int ch    = j >> 12;
        int row   = mtile * 128 + w * 32 + mt * 16 + (lane >> 2) + (r & 1) * 8;
        int kbase = ks * 16 + (lane & 3) * 2 + (r >> 1) * 8;
        uint32_t outv = 0;
#pragma unroll
        for (int h = 0; h < 2; ++h) {
            int ci = kbase + h;    // 0..31
            float v = l1sel
                ? w1[((size_t)row * 64 + (ch & 1) * 32 + ci) * 9 + (ch >> 1)]
                : w0[((size_t)row * 32 + ci) * 9 + ch];
            outv |= (uint32_t)__half_as_ushort(__float2half_rn(v)) << (16 * h);
        }
        (l1sel ? g_wf1 : g_wf0)[j] = outv;
    }
}

// ---------------- GEMM kernel ----------------
// CTA = 128 threads (4 warps). Tile: M=128 gate channels x N=64 padded pixels,
// one frame. Chunks of 32 ci (K=32, 2 k-steps). A fragments straight from
// fragment-ordered gmem (L2-resident LDG.128); B streamed via cp.async,
// prefetch distance 2, 4-buffer ring, one __syncthreads per chunk.
template <int CPT>   // chunks per tap: 1 (CIN=32) or 2 (CIN=64)
__device__ __forceinline__ void gemm_body(const __half* __restrict__ bpl,
                                          const uint32_t* __restrict__ wf,
                                          float* __restrict__ gates)
{
    __shared__ __align__(16) __half sBt[4][32 * BST];   // 18.4 KB total

    const int tid  = threadIdx.x, w = tid >> 5, lane = tid & 31;
    const int frame = blockIdx.x / NT, ntile = blockIdx.x - frame * NT;
    const int mtile = blockIdx.y;
    const int p0 = ntile * 64;
    const int NCH = 9 * CPT;

    const size_t fbase = (size_t)frame * (CPT * 32) * 7;
    const int cis = tid >> 3, gs = tid & 7;      // staging coords: 16 ci x 8 chunks

    // async B chunk copy (2 x 16B per thread)
    auto copyB = [&](int ch) {
        const int tap = (CPT == 1) ? ch : (ch >> 1);
        const int ci0 = (CPT == 1) ? 0 : ((ch & 1) * 32);
        const __half* bp = bpl + (fbase + (size_t)ci0 * 7 + c_q[tap]) * PLST
                         + p0 + c_off[tap];
        uint32_t sa = smem_u32(sBt[ch & 3]) + (uint32_t)(cis * BST + gs * 8) * 2;
        cp16(sa,                    bp + (size_t)cis * (7 * PLST) + gs * 8);
        cp16(sa + 16 * BST * 2,     bp + (size_t)(cis + 16) * (7 * PLST) + gs * 8);
    };

    float d[2][8][4];
#pragma unroll
    for (int mt = 0; mt < 2; ++mt)
#pragma unroll
        for (int nt = 0; nt < 8; ++nt)
#pragma unroll
            for (int q = 0; q < 4; ++q) d[mt][nt][q] = 0.0f;

    // ---- pipeline prologue: chunks 0,1 in flight ----
    copyB(0); cp_commit();
    copyB(1); cp_commit();

#pragma unroll 1
    for (int ch = 0; ch < NCH; ++ch) {
        // ---- prefetch chunk ch+2 (empty commit keeps group count aligned) ----
        if (ch + 2 < NCH) copyB(ch + 2);
        cp_commit();

        // ---- A fragments for this chunk: 4 independent LDG.128 (L2) ----
        const uint4* af = (const uint4*)wf
                        + ((size_t)(ch * 2 + mtile) * 4 + w) * 128 + lane;
        uint4 afr[2][2];
#pragma unroll
        for (int mt = 0; mt < 2; ++mt)
#pragma unroll
            for (int ks = 0; ks < 2; ++ks)
                afr[mt][ks] = af[(mt * 2 + ks) * 32];

        // ---- wait for chunk ch, make visible ----
        cp_wait2();
        __syncthreads();

        // ---- B fragments via ldmatrix.trans ----
        const uint32_t sBu = smem_u32(sBt[ch & 3]);
        uint32_t bfr[2][4][4];
#pragma unroll
        for (int kk = 0; kk < 2; ++kk)
#pragma unroll
            for (int np = 0; np < 4; ++np) {
                int ci = kk * 16 + ((lane >> 3) & 1) * 8 + (lane & 7);
                int px = np * 16 + (lane >> 4) * 8;
                ldsm4t(bfr[kk][np], sBu + (uint32_t)(ci * BST + px) * 2);
            }

        // ---- mma: 2 k-steps of 16 ----
#pragma unroll
        for (int ks = 0; ks < 2; ++ks) {
#pragma unroll
            for (int mt = 0; mt < 2; ++mt) {
                const uint4 a = afr[mt][ks];
#pragma unroll
                for (int nt = 0; nt < 8; ++nt)
                    mma16816(d[mt][nt], a.x, a.y, a.z, a.w,
                             bfr[ks][nt >> 1][(nt & 1) * 2],
                             bfr[ks][nt >> 1][(nt & 1) * 2 + 1]);
            }
        }
    }

    // ---- epilogue: D -> gates scratch ----
    const int g4 = lane >> 2, t4 = lane & 3;
#pragma unroll
    for (int mt = 0; mt < 2; ++mt) {
        size_t rowbase = (size_t)frame * 256 + mtile * 128 + w * 32 + mt * 16 + g4;
#pragma unroll
        for (int nt = 0; nt < 8; ++nt) {
            float* gp = gates + rowbase * GST + p0 + nt * 8 + t4 * 2;
            *(float2*)gp                     = make_float2(d[mt][nt][0], d[mt][nt][1]);
            *(float2*)(gp + 8 * (size_t)GST) = make_float2(d[mt][nt][2], d[mt][nt][3]);
        }
    }
}

__global__ void __launch_bounds__(128, 4)
k_gemm0() { gemm_body<1>(g_x7 + 64, g_wf0, g_gates); }

__global__ void __launch_bounds__(128, 4)
k_gemm1() { gemm_body<2>(g_h7 + 64, g_wf1, g_gates); }

// ---------------- scan kernels ----------------
// thread = (b, lstm-channel, interior pixel); loops s, cell state in register.
// PADOUT=true writes the 7 shifted fp16 plane copies for the next GEMM.
template <bool PADOUT>
__global__ void __launch_bounds__(256)
k_scan(const float* __restrict__ bias, float* __restrict__ out)
{
    int gtid = blockIdx.x * blockDim.x + threadIdx.x;  // 0 .. 262143
    int px = gtid & 1023;
    int ch = (gtid >> 10) & 63;
    int b  = gtid >> 16;
    int r = px >> 5, c = px & 31;
    int p = (r + 1) * 34 + (c + 1);

    float bi = __ldg(bias + ch);
    float bf = __ldg(bias + 64 + ch);
    float bo = __ldg(bias + 128 + ch);
    float bc = __ldg(bias + 192 + ch);

    float cst = 0.5f;
    __half* h7 = g_h7 + 64;

#pragma unroll 1
    for (int s = 0; s < S_; ++s) {
        int frame = b * S_ + s;
        const float* gg = g_gates + (size_t)frame * 256 * GST + p;
        float it = sigm(gg[(size_t)(ch)       * GST] + bi);
        float ft = sigm(gg[(size_t)(64 + ch)  * GST] + bf);
        float ot = sigm(gg[(size_t)(128 + ch) * GST] + bo);
        float cd =      gg[(size_t)(192 + ch) * GST] + bc;
        float gd = (cd >= 0.0f) ? (cd + 0.5f) : sigm(cd);
        float inv = 1.0f / (it + ft);
        cst = (ft * inv) * cst + (it * inv) * gd;
        float hv = ot * cst;
        if (PADOUT) {
            __half h16 = __float2half_rn(hv);
            __half* base = h7 + ((size_t)frame * CL_ + ch) * 7 * PLST;
#pragma unroll
            for (int q = 0; q < 7; ++q)
                base[q * PLST + p - c_tq[q]] = h16;
        } else {
            out[((size_t)frame * CL_ + ch) * HW_ + px] = hv;
        }
    }
}

// ---------------- launch ----------------
extern "C" void kernel_launch(void* const* d_in, const int* in_sizes, int n_in,
                              void* d_out, int out_size)
{
    const float* x  = (const float*)d_in[0];
    const float* w0 = (const float*)d_in[1];
    const float* b0 = (const float*)d_in[2];
    const float* w1 = (const float*)d_in[3];
    const float* b1 = (const float*)d_in[4];
    float* out = (float*)d_out;

    k_fill_x7<<<2048, 256>>>(x);
    k_pack_wf<<<512, 256>>>(w0, w1);

    dim3 gg(NF * NT, 2, 1);   // 1152 x 2 CTAs
    k_gemm0<<<gg, 128>>>();
    k_scan<true><<<1024, 256>>>(b0, nullptr);
    k_gemm1<<<gg, 128>>>();
    k_scan<false><<<1024, 256>>>(b1, out);
}

// round 14
// speedup vs baseline: 1.6303x; 1.0507x over previous
#include <cuda_runtime.h>
#include <cuda_fp16.h>
#include <cstdint>

// ---------------- problem constants ----------------
#define B_     4
#define S_     16
#define NF     64            // frames = B*S
#define H_     32
#define W_     32
#define HW_    1024
#define CL_    64            // LSTM channels per layer; gate channels = 256
#define GST    1152          // gates scratch stride (18 N-tiles of 64)
#define NT     18            // N tiles per frame
#define PLST   1160          // halves per plane copy
#define NCPY   2             // copies per plane (shift 0 / shift 1)
#define BST    72            // B smem row stride in halves

// ---------------- device scratch (static; no allocations) ----------------
// NOTE: __device__ globals are zero-initialized at module load. Interiors are
// rewritten every launch; halo/guard positions are NEVER written by any
// kernel, so they stay zero across all launches -> no zeroing pass needed.
__device__ float g_gates[(size_t)NF * 256 * GST];                 // conv outputs
// 2 shifted fp16 padded-plane copies (shift 0 and 1) of x and of h0 (+guards)
__device__ __align__(16) __half g_x7[(size_t)NF * 32 * NCPY * PLST + 64 + 2048];
__device__ __align__(16) __half g_h7[(size_t)NF * 64 * NCPY * PLST + 64 + 2048];
// fragment-ordered fp16 weights (single precision term):
// [chunk][mtile(2)][warp(4)][mt(2)][ks(2)][lane(32)][4 u32]
__device__ __align__(16) uint32_t g_wf0[9  * 4096];
__device__ __align__(16) uint32_t g_wf1[18 * 4096];

// taps in order {-35,-34,-33,-1,0,1,33,34,35}:
// copy q = tap&1; effective (even) offset = tap - q.
__constant__ int c_q[9]   = { 1, 0, 1, 1, 0, 1, 1, 0, 1 };
__constant__ int c_off[9] = { -36, -34, -34, -2, 0, 0, 32, 34, 34 };

// ---------------- helpers ----------------
__device__ __forceinline__ float sigm(float x) { return 1.0f / (1.0f + __expf(-x)); }

__device__ __forceinline__ uint32_t smem_u32(const void* p) {
    uint32_t a;
    asm("{ .reg .u64 t; cvta.to.shared.u64 t, %1; cvt.u32.u64 %0, t; }" : "=r"(a) : "l"(p));
    return a;
}

__device__ __forceinline__ void cp4(uint32_t saddr, const void* gptr) {
    asm volatile("cp.async.ca.shared.global [%0], [%1], 4;"
                 :: "r"(saddr), "l"(gptr) : "memory");
}
__device__ __forceinline__ void cp_commit() {
    asm volatile("cp.async.commit_group;" ::: "memory");
}
__device__ __forceinline__ void cp_wait2() {
    asm volatile("cp.async.wait_group 2;" ::: "memory");
}

__device__ __forceinline__ void ldsm4t(uint32_t r[4], uint32_t addr) {
    asm volatile("ldmatrix.sync.aligned.m8n8.x4.trans.shared.b16 {%0,%1,%2,%3}, [%4];"
        : "=r"(r[0]), "=r"(r[1]), "=r"(r[2]), "=r"(r[3]) : "r"(addr));
}

__device__ __forceinline__ void mma16816(float d[4], uint32_t a0, uint32_t a1,
                                         uint32_t a2, uint32_t a3,
                                         uint32_t b0, uint32_t b1) {
    asm volatile(
        "mma.sync.aligned.m16n8k16.row.col.f32.f16.f16.f32 "
        "{%0,%1,%2,%3}, {%4,%5,%6,%7}, {%8,%9}, {%0,%1,%2,%3};"
        : "+f"(d[0]), "+f"(d[1]), "+f"(d[2]), "+f"(d[3])
        : "r"(a0), "r"(a1), "r"(a2), "r"(a3), "r"(b0), "r"(b1));
}

// ---------------- prologue kernels ----------------
// build the 2 shifted fp16 copies of padded x planes (interior positions only)
__global__ void k_fill_x7(const float* __restrict__ x) {
    __half* xb = g_x7 + 64;
    const int n = NF * 32 * HW_;
    for (int i = blockIdx.x * blockDim.x + threadIdx.x; i < n;
         i += gridDim.x * blockDim.x) {
        int plane = i >> 10, px = i & 1023;
        int r = px >> 5, c = px & 31;
        int p = (r + 1) * 34 + (c + 1);
        __half hv = __float2half_rn(x[i]);
        __half* base = xb + (size_t)plane * NCPY * PLST;
        base[p] = hv;               // copy0 (shift 0)
        base[PLST + p - 1] = hv;    // copy1 (shift 1)
    }
}

// pack weights directly into mma A-fragment order (single fp16 term).
// fragment layout (m16n8k16, row-major A): lane l, reg r:
//   row = (l>>2) + (r&1)*8 ; cols = (l&3)*2 + (r>>1)*8 + {0,1}
__global__ void k_pack_wf(const float* __restrict__ w0, const float* __restrict__ w1) {
    const int n0 = 9 * 4096, n1 = 18 * 4096;
    for (int i = blockIdx.x * blockDim.x + threadIdx.x; i < n0 + n1;
         i += gridDim.x * blockDim.x) {
        bool l1sel = (i >= n0);
        int j = l1sel ? (i - n0) : i;
        int r     = j & 3;
        int lane  = (j >> 2) & 31;
        int ks    = (j >> 7) & 1;
        int mt    = (j >> 8) & 1;
        int w     = (j >> 9) & 3;
        int mtile = (j >> 11) & 1;
        int ch    = j >> 12;
        int row   = mtile * 128 + w * 32 + mt * 16 + (lane >> 2) + (r & 1) * 8;
        int kbase = ks * 16 + (lane & 3) * 2 + (r >> 1) * 8;
        uint32_t outv = 0;
#pragma unroll
        for (int h = 0; h < 2; ++h) {
            int ci = kbase + h;    // 0..31
            float v = l1sel
                ? w1[((size_t)row * 64 + (ch & 1) * 32 + ci) * 9 + (ch >> 1)]
                : w0[((size_t)row * 32 + ci) * 9 + ch];
            outv |= (uint32_t)__half_as_ushort(__float2half_rn(v)) << (16 * h);
        }
        (l1sel ? g_wf1 : g_wf0)[j] = outv;
    }
}

// ---------------- GEMM kernel ----------------
// CTA = 128 threads (4 warps). Tile: M=128 gate channels x N=64 padded pixels,
// one frame. Chunks of 32 ci (K=32, 2 k-steps). A fragments straight from
// fragment-ordered gmem (L2-resident LDG.128); B streamed via 4-byte cp.async
// from the 2 shifted copies, prefetch distance 2, 4-buffer ring.
template <int CPT>   // chunks per tap: 1 (CIN=32) or 2 (CIN=64)
__device__ __forceinline__ void gemm_body(const __half* __restrict__ bpl,
                                          const uint32_t* __restrict__ wf,
                                          float* __restrict__ gates)
{
    __shared__ __align__(16) __half sBt[4][32 * BST];   // 18.4 KB total

    const int tid  = threadIdx.x, w = tid >> 5, lane = tid & 31;
    const int frame = blockIdx.x / NT, ntile = blockIdx.x - frame * NT;
    const int mtile = blockIdx.y;
    const int p0 = ntile * 64;
    const int NCH = 9 * CPT;
    constexpr int CIN = CPT * 32;

    const int cis = tid >> 3, gs = tid & 7;      // staging coords: 16 ci x 8 chunks

    // async B chunk copy (8 x 4B per thread)
    auto copyB = [&](int ch) {
        const int tap = (CPT == 1) ? ch : (ch >> 1);
        const int ci0 = (CPT == 1) ? 0 : ((ch & 1) * 32);
        const __half* bp = bpl
            + ((size_t)(frame * CIN + ci0) * NCPY + c_q[tap]) * PLST
            + p0 + c_off[tap];
        uint32_t sa = smem_u32(sBt[ch & 3]);
#pragma unroll
        for (int rr = 0; rr < 2; ++rr) {
            int r = cis + rr * 16;
            const __half* src = bp + (size_t)r * (NCPY * PLST) + gs * 8;
            uint32_t dst = sa + (uint32_t)(r * BST + gs * 8) * 2;
#pragma unroll
            for (int jj = 0; jj < 4; ++jj)
                cp4(dst + jj * 4, src + jj * 2);
        }
    };

    float d[2][8][4];
#pragma unroll
    for (int mt = 0; mt < 2; ++mt)
#pragma unroll
        for (int nt = 0; nt < 8; ++nt)
#pragma unroll
            for (int q = 0; q < 4; ++q) d[mt][nt][q] = 0.0f;

    // ---- pipeline prologue: chunks 0,1 in flight ----
    copyB(0); cp_commit();
    copyB(1); cp_commit();

#pragma unroll 1
    for (int ch = 0; ch < NCH; ++ch) {
        // ---- prefetch chunk ch+2 (empty commit keeps group count aligned) ----
        if (ch + 2 < NCH) copyB(ch + 2);
        cp_commit();

        // ---- A fragments for this chunk: 4 independent LDG.128 (L2) ----
        const uint4* af = (const uint4*)wf
                        + ((size_t)(ch * 2 + mtile) * 4 + w) * 128 + lane;
        uint4 afr[2][2];
#pragma unroll
        for (int mt = 0; mt < 2; ++mt)
#pragma unroll
            for (int ks = 0; ks < 2; ++ks)
                afr[mt][ks] = af[(mt * 2 + ks) * 32];

        // ---- wait for chunk ch, make visible ----
        cp_wait2();
        __syncthreads();

        // ---- B fragments via ldmatrix.trans ----
        const uint32_t sBu = smem_u32(sBt[ch & 3]);
        uint32_t bfr[2][4][4];
#pragma unroll
        for (int kk = 0; kk < 2; ++kk)
#pragma unroll
            for (int np = 0; np < 4; ++np) {
                int ci = kk * 16 + ((lane >> 3) & 1) * 8 + (lane & 7);
                int px = np * 16 + (lane >> 4) * 8;
                ldsm4t(bfr[kk][np], sBu + (uint32_t)(ci * BST + px) * 2);
            }

        // ---- mma: 2 k-steps of 16 ----
#pragma unroll
        for (int ks = 0; ks < 2; ++ks) {
#pragma unroll
            for (int mt = 0; mt < 2; ++mt) {
                const uint4 a = afr[mt][ks];
#pragma unroll
                for (int nt = 0; nt < 8; ++nt)
                    mma16816(d[mt][nt], a.x, a.y, a.z, a.w,
                             bfr[ks][nt >> 1][(nt & 1) * 2],
                             bfr[ks][nt >> 1][(nt & 1) * 2 + 1]);
            }
        }
    }

    // ---- epilogue: D -> gates scratch ----
    const int g4 = lane >> 2, t4 = lane & 3;
#pragma unroll
    for (int mt = 0; mt < 2; ++mt) {
        size_t rowbase = (size_t)frame * 256 + mtile * 128 + w * 32 + mt * 16 + g4;
#pragma unroll
        for (int nt = 0; nt < 8; ++nt) {
            float* gp = gates + rowbase * GST + p0 + nt * 8 + t4 * 2;
            *(float2*)gp                     = make_float2(d[mt][nt][0], d[mt][nt][1]);
            *(float2*)(gp + 8 * (size_t)GST) = make_float2(d[mt][nt][2], d[mt][nt][3]);
        }
    }
}

__global__ void __launch_bounds__(128, 4)
k_gemm0() { gemm_body<1>(g_x7 + 64, g_wf0, g_gates); }

__global__ void __launch_bounds__(128, 4)
k_gemm1() { gemm_body<2>(g_h7 + 64, g_wf1, g_gates); }

// ---------------- scan kernels ----------------
// thread = (b, lstm-channel, interior pixel); loops s, cell state in register.
// Software-pipelined: frame s+1's gates loaded while computing frame s.
// PADOUT=true writes the 2 shifted fp16 plane copies for the next GEMM.
template <bool PADOUT>
__global__ void __launch_bounds__(256)
k_scan(const float* __restrict__ bias, float* __restrict__ out)
{
    int gtid = blockIdx.x * blockDim.x + threadIdx.x;  // 0 .. 262143
    int px = gtid & 1023;
    int ch = (gtid >> 10) & 63;
    int b  = gtid >> 16;
    int r = px >> 5, c = px & 31;
    int p = (r + 1) * 34 + (c + 1);

    float bi = __ldg(bias + ch);
    float bf = __ldg(bias + 64 + ch);
    float bo = __ldg(bias + 128 + ch);
    float bc = __ldg(bias + 192 + ch);

    float cst = 0.5f;
    __half* h7 = g_h7 + 64;

    const float* gg0 = g_gates + (size_t)(b * S_) * 256 * GST + (size_t)ch * GST + p;
    const size_t fstep = (size_t)256 * GST;

    float vi = gg0[0];
    float vf = gg0[64 * (size_t)GST];
    float vo = gg0[128 * (size_t)GST];
    float vc = gg0[192 * (size_t)GST];

#pragma unroll 1
    for (int s = 0; s < S_; ++s) {
        float ni = 0.f, nf = 0.f, no = 0.f, nc = 0.f;
        if (s + 1 < S_) {
            const float* gn = gg0 + (size_t)(s + 1) * fstep;
            ni = gn[0];
            nf = gn[64 * (size_t)GST];
            no = gn[128 * (size_t)GST];
            nc = gn[192 * (size_t)GST];
        }
        float it = sigm(vi + bi);
        float ft = sigm(vf + bf);
        float ot = sigm(vo + bo);
        float cd = vc + bc;
        float gd = (cd >= 0.0f) ? (cd + 0.5f) : sigm(cd);
        float inv = 1.0f / (it + ft);
        cst = (ft * inv) * cst + (it * inv) * gd;
        float hv = ot * cst;
        int frame = b * S_ + s;
        if (PADOUT) {
            __half h16 = __float2half_rn(hv);
            __half* base = h7 + ((size_t)frame * CL_ + ch) * NCPY * PLST;
            base[p] = h16;               // copy0 (shift 0)
            base[PLST + p - 1] = h16;    // copy1 (shift 1)
        } else {
            out[((size_t)frame * CL_ + ch) * HW_ + px] = hv;
        }
        vi = ni; vf = nf; vo = no; vc = nc;
    }
}

// ---------------- launch ----------------
extern "C" void kernel_launch(void* const* d_in, const int* in_sizes, int n_in,
                              void* d_out, int out_size)
{
    const float* x  = (const float*)d_in[0];
    const float* w0 = (const float*)d_in[1];
    const float* b0 = (const float*)d_in[2];
    const float* w1 = (const float*)d_in[3];
    const float* b1 = (const float*)d_in[4];
    float* out = (float*)d_out;

    k_fill_x7<<<2048, 256>>>(x);
    k_pack_wf<<<512, 256>>>(w0, w1);

    dim3 gg(NF * NT, 2, 1);   // 1152 x 2 CTAs
    k_gemm0<<<gg, 128>>>();
    k_scan<true><<<1024, 256>>>(b0, nullptr);
    k_gemm1<<<gg, 128>>>();
    k_scan<false><<<1024, 256>>>(b1, out);
}